// round 7
// baseline (speedup 1.0000x reference)
#include <cuda_runtime.h>
#include <cstdint>
#include <math.h>

// Problem constants
#define HID   4096
#define NB    4
#define QLEN  1024
#define NH    32
#define NKV   8
#define HD    128
#define PAST  1024
#define KVLEN 2048
#define MROWS (NB*QLEN)   // 4096
#define QSCALE 0.08838834764831845f
#define NEGBIG (-1.0e9f)

// GEMM tiling (mma.sync tf32): 128x64 CTA tile, BK=16, 8 warps (4x2), warp 32x32
#define BM 128
#define BN 64
#define BK 16
#define NKITER (HID/BK)     // 256
#define SST 20              // smem row stride in floats (conflict-free)
#define ATILE (BM*SST)      // 2560 floats
#define BTILE (BN*SST)      // 1280 floats
#define GSMEM ((2*ATILE + 2*BTILE)*4)   // 30720 bytes

// Attention tiling (unchanged from R6-passing kernel)
#define AQ  128
#define AKV 64
#define QST 132
#define VST 68
#define ATTN_SM_BYTES ((128*QST + 64*QST + 128*VST + 128*VST + 64) * 4)

// Scratch (device globals — allocation-free)
__device__ float g_q   [(size_t)NB*NH *QLEN*HD];   // [B,H,S,D]
__device__ float g_kn  [(size_t)NB*NKV*QLEN*HD];   // [B,Hkv,S,D]
__device__ float g_vn  [(size_t)NB*NKV*QLEN*HD];   // [B,Hkv,S,D]
__device__ float g_attn[(size_t)MROWS*HID];        // [B*S, H*D]

// ---------------------------------------------------------------------------
__device__ __forceinline__ float f2tf32(float x){
    uint32_t r; asm("cvt.rna.tf32.f32 %0, %1;" : "=r"(r) : "f"(x));
    return __uint_as_float(r);
}
__device__ __forceinline__ void mma8(float* d, const uint32_t* a, const uint32_t* b){
    asm volatile(
        "mma.sync.aligned.m16n8k8.row.col.f32.tf32.tf32.f32 "
        "{%0,%1,%2,%3}, {%4,%5,%6,%7}, {%8,%9}, {%0,%1,%2,%3};"
        : "+f"(d[0]), "+f"(d[1]), "+f"(d[2]), "+f"(d[3])
        : "r"(a[0]), "r"(a[1]), "r"(a[2]), "r"(a[3]), "r"(b[0]), "r"(b[1]));
}

// ---------------------------------------------------------------------------
// GEMM mainloop: C[128x64] = A[128 x 4096] @ B^T (B row-major [64][4096])
// 8 warps: wm = w&3 (M tile of 32), wn = w>>2 (N tile of 32).
// ---------------------------------------------------------------------------
__device__ __forceinline__ void gemm_mainloop(
    const float* __restrict__ Ag, const float* __restrict__ Bg,
    float (&acc)[2][4][4])
{
    extern __shared__ float sm[];
    float* Abuf[2] = { sm,            sm + ATILE };
    float* Bbuf[2] = { sm + 2*ATILE,  sm + 2*ATILE + BTILE };

    const int tid  = threadIdx.x;
    const int lane = tid & 31;
    const int w    = tid >> 5;
    const int wm   = w & 3;
    const int wn   = w >> 2;
    const int lq   = lane >> 2;
    const int lr4  = lane & 3;

    #pragma unroll
    for (int mt = 0; mt < 2; mt++)
        #pragma unroll
        for (int nt = 0; nt < 4; nt++)
            #pragma unroll
            for (int c = 0; c < 4; c++) acc[mt][nt][c] = 0.f;

    // staging: A = 512 float4 (2/thread), B = 256 float4 (1/thread)
    const int r0 = tid >> 2, c0 = (tid & 3) * 4;

    float4 ra[2], rb;
    auto ld_tile = [&](int k0){
        ra[0] = *reinterpret_cast<const float4*>(Ag + (size_t)r0*HID + k0 + c0);
        ra[1] = *reinterpret_cast<const float4*>(Ag + (size_t)(r0+64)*HID + k0 + c0);
        rb    = *reinterpret_cast<const float4*>(Bg + (size_t)r0*HID + k0 + c0);
    };
    auto st_tile = [&](float* As, float* Bs){
        float4 v;
        v.x=f2tf32(ra[0].x); v.y=f2tf32(ra[0].y); v.z=f2tf32(ra[0].z); v.w=f2tf32(ra[0].w);
        *reinterpret_cast<float4*>(As + r0*SST + c0) = v;
        v.x=f2tf32(ra[1].x); v.y=f2tf32(ra[1].y); v.z=f2tf32(ra[1].z); v.w=f2tf32(ra[1].w);
        *reinterpret_cast<float4*>(As + (r0+64)*SST + c0) = v;
        v.x=f2tf32(rb.x);    v.y=f2tf32(rb.y);    v.z=f2tf32(rb.z);    v.w=f2tf32(rb.w);
        *reinterpret_cast<float4*>(Bs + r0*SST + c0) = v;
    };

    ld_tile(0);
    st_tile(Abuf[0], Bbuf[0]);
    __syncthreads();

    for (int kt = 0; kt < NKITER; kt++) {
        const bool last = (kt == NKITER - 1);
        if (!last) ld_tile((kt + 1) * BK);

        const float* As = Abuf[kt & 1];
        const float* Bs = Bbuf[kt & 1];
        #pragma unroll
        for (int ks = 0; ks < 2; ks++) {
            const int kk = ks * 8;
            uint32_t af[2][4], bf[4][2];
            #pragma unroll
            for (int mt = 0; mt < 2; mt++) {
                const int base = (wm*32 + mt*16 + lq)*SST + kk + lr4;
                af[mt][0] = __float_as_uint(As[base]);
                af[mt][1] = __float_as_uint(As[base + 8*SST]);
                af[mt][2] = __float_as_uint(As[base + 4]);
                af[mt][3] = __float_as_uint(As[base + 8*SST + 4]);
            }
            #pragma unroll
            for (int nt = 0; nt < 4; nt++) {
                const int nb = (wn*32 + nt*8 + lq)*SST + kk + lr4;
                bf[nt][0] = __float_as_uint(Bs[nb]);
                bf[nt][1] = __float_as_uint(Bs[nb + 4]);
            }
            #pragma unroll
            for (int mt = 0; mt < 2; mt++)
                #pragma unroll
                for (int nt = 0; nt < 4; nt++)
                    mma8(acc[mt][nt], af[mt], bf[nt]);
        }
        if (!last) st_tile(Abuf[(kt+1) & 1], Bbuf[(kt+1) & 1]);
        __syncthreads();
    }
}

// ---------------------------------------------------------------------------
// QKV projection: virtual N = 6144 in 64-col tiles (q 0..63 | k 64..79 | v 80..95)
// ---------------------------------------------------------------------------
__global__ void __launch_bounds__(256, 3) qkv_mma(
    const float* __restrict__ X,
    const float* __restrict__ Wq, const float* __restrict__ bq,
    const float* __restrict__ Wk, const float* __restrict__ bk,
    const float* __restrict__ Wv, const float* __restrict__ bv)
{
    const int m0  = blockIdx.x * BM;
    const int n0e = blockIdx.y * BN;
    const float* W; const float* bias; int sel, nl0;
    if (n0e < 4096)      { W = Wq; bias = bq; sel = 0; nl0 = n0e; }
    else if (n0e < 5120) { W = Wk; bias = bk; sel = 1; nl0 = n0e - 4096; }
    else                 { W = Wv; bias = bv; sel = 2; nl0 = n0e - 5120; }

    float acc[2][4][4];
    gemm_mainloop(X + (size_t)m0*HID, W + (size_t)nl0*HID, acc);

    const int lane = threadIdx.x & 31, w = threadIdx.x >> 5;
    const int wm = w & 3, wn = w >> 2;
    const int lq = lane >> 2, lr4 = lane & 3;

    #pragma unroll
    for (int mt = 0; mt < 2; mt++) {
        #pragma unroll
        for (int half = 0; half < 2; half++) {
            const int gm = m0 + wm*32 + mt*16 + lq + half*8;
            const int bb = gm >> 10, sq = gm & 1023;
            #pragma unroll
            for (int nt = 0; nt < 4; nt++) {
                const int nl = nl0 + wn*32 + nt*8 + lr4*2;
                const float2 bv2 = *reinterpret_cast<const float2*>(bias + nl);
                float2 v;
                v.x = acc[mt][nt][half*2 + 0] + bv2.x;
                v.y = acc[mt][nt][half*2 + 1] + bv2.y;
                const int h = nl >> 7, d = nl & 127;
                float* dst;
                if (sel == 0)      dst = &g_q [(((size_t)bb*NH  + h)*QLEN + sq)*HD + d];
                else if (sel == 1) dst = &g_kn[(((size_t)bb*NKV + h)*QLEN + sq)*HD + d];
                else               dst = &g_vn[(((size_t)bb*NKV + h)*QLEN + sq)*HD + d];
                *reinterpret_cast<float2*>(dst) = v;
            }
        }
    }
}

// ---------------------------------------------------------------------------
// Output projection: out = g_attn @ Wo^T + bo
// ---------------------------------------------------------------------------
__global__ void __launch_bounds__(256, 3) out_mma(
    const float* __restrict__ Wo, const float* __restrict__ bo,
    float* __restrict__ out)
{
    const int m0 = blockIdx.x * BM;
    const int n0 = blockIdx.y * BN;

    float acc[2][4][4];
    gemm_mainloop(g_attn + (size_t)m0*HID, Wo + (size_t)n0*HID, acc);

    const int lane = threadIdx.x & 31, w = threadIdx.x >> 5;
    const int wm = w & 3, wn = w >> 2;
    const int lq = lane >> 2, lr4 = lane & 3;

    #pragma unroll
    for (int mt = 0; mt < 2; mt++) {
        #pragma unroll
        for (int half = 0; half < 2; half++) {
            const int gm = m0 + wm*32 + mt*16 + lq + half*8;
            #pragma unroll
            for (int nt = 0; nt < 4; nt++) {
                const int gn = n0 + wn*32 + nt*8 + lr4*2;
                const float2 bv2 = *reinterpret_cast<const float2*>(bo + gn);
                float2 v;
                v.x = acc[mt][nt][half*2 + 0] + bv2.x;
                v.y = acc[mt][nt][half*2 + 1] + bv2.y;
                *reinterpret_cast<float2*>(out + (size_t)gm*HID + gn) = v;
            }
        }
    }
}

// ---------------------------------------------------------------------------
// Flash attention on mma.sync tf32 (unchanged from R6-passing kernel)
// ---------------------------------------------------------------------------
__global__ void __launch_bounds__(256, 1) attn_mma(
    const float* __restrict__ pastK, const float* __restrict__ pastV,
    const int* __restrict__ amask)
{
    extern __shared__ float sm[];
    float* Qs = sm;                    // [128][QST]
    float* Ks = Qs + 128*QST;          // [64][QST]
    float* Vt = Ks + 64*QST;           // [128][VST]
    float* Ps = Vt + 128*VST;          // [128][VST]
    float* mb = Ps + 128*VST;          // [64]

    const int b = blockIdx.z, h = blockIdx.y, q0 = blockIdx.x * AQ;
    const int hkv = h >> 2;
    const int tid = threadIdx.x;
    const int lane = tid & 31, w = tid >> 5;
    const int lq = lane >> 2, lr4 = lane & 3;
    const int qrow = w*16 + lq;

    {
        const int r = tid >> 1;
        const int cb = (tid & 1) * 64;
        const float* Qg = g_q + (((size_t)b*NH + h)*QLEN + q0 + r) * HD + cb;
        #pragma unroll
        for (int i = 0; i < 16; i++) {
            float4 q = *reinterpret_cast<const float4*>(Qg + i*4);
            float4 v;
            v.x = f2tf32(q.x * QSCALE); v.y = f2tf32(q.y * QSCALE);
            v.z = f2tf32(q.z * QSCALE); v.w = f2tf32(q.w * QSCALE);
            *reinterpret_cast<float4*>(Qs + r*QST + cb + i*4) = v;
        }
    }

    float oacc[16][4];
    #pragma unroll
    for (int d = 0; d < 16; d++)
        #pragma unroll
        for (int c = 0; c < 4; c++) oacc[d][c] = 0.f;
    float m0 = -3.0e38f, m1 = -3.0e38f, l0 = 0.f, l1 = 0.f;

    const float* Kgp = pastK + ((size_t)b*NKV + hkv) * PAST * HD;
    const float* Vgp = pastV + ((size_t)b*NKV + hkv) * PAST * HD;
    const float* Kgn = g_kn  + ((size_t)b*NKV + hkv) * QLEN * HD;
    const float* Vgn = g_vn  + ((size_t)b*NKV + hkv) * QLEN * HD;
    const int*   mg  = amask + (size_t)b * KVLEN;

    for (int kt = 0; kt < 32; kt++) {
        __syncthreads();
        {
            const int r = tid & 63, c4 = tid >> 6;
            const int p = kt*64 + r;
            const float* krow = (p < PAST) ? (Kgp + (size_t)p*HD) : (Kgn + (size_t)(p-PAST)*HD);
            const float* vrow = (p < PAST) ? (Vgp + (size_t)p*HD) : (Vgn + (size_t)(p-PAST)*HD);
            #pragma unroll
            for (int i = 0; i < 8; i++) {
                const int cc = (c4 + i*4) * 4;
                float4 k4 = *reinterpret_cast<const float4*>(krow + cc);
                float4 kv;
                kv.x = f2tf32(k4.x); kv.y = f2tf32(k4.y);
                kv.z = f2tf32(k4.z); kv.w = f2tf32(k4.w);
                *reinterpret_cast<float4*>(Ks + r*QST + cc) = kv;
                float4 v4 = *reinterpret_cast<const float4*>(vrow + cc);
                Vt[(cc+0)*VST + r] = f2tf32(v4.x);
                Vt[(cc+1)*VST + r] = f2tf32(v4.y);
                Vt[(cc+2)*VST + r] = f2tf32(v4.z);
                Vt[(cc+3)*VST + r] = f2tf32(v4.w);
            }
            if (tid < 64) mb[tid] = (mg[kt*64 + tid] == 0) ? 0.f : NEGBIG;
        }
        __syncthreads();

        float sacc[8][4];
        #pragma unroll
        for (int nt = 0; nt < 8; nt++)
            #pragma unroll
            for (int c = 0; c < 4; c++) sacc[nt][c] = 0.f;
        #pragma unroll
        for (int ks = 0; ks < 16; ks++) {
            const int k = ks*8 + lr4;
            uint32_t af[4];
            af[0] = __float_as_uint(Qs[qrow*QST + k]);
            af[1] = __float_as_uint(Qs[(qrow+8)*QST + k]);
            af[2] = __float_as_uint(Qs[qrow*QST + k + 4]);
            af[3] = __float_as_uint(Qs[(qrow+8)*QST + k + 4]);
            #pragma unroll
            for (int nt = 0; nt < 8; nt++) {
                uint32_t bf[2];
                bf[0] = __float_as_uint(Ks[(nt*8 + lq)*QST + k]);
                bf[1] = __float_as_uint(Ks[(nt*8 + lq)*QST + k + 4]);
                mma8(sacc[nt], af, bf);
            }
        }

        float tmax0 = -3.0e38f, tmax1 = -3.0e38f;
        #pragma unroll
        for (int nt = 0; nt < 8; nt++) {
            const float b0 = mb[nt*8 + lr4*2], b1 = mb[nt*8 + lr4*2 + 1];
            sacc[nt][0] += b0; sacc[nt][1] += b1;
            sacc[nt][2] += b0; sacc[nt][3] += b1;
            tmax0 = fmaxf(tmax0, fmaxf(sacc[nt][0], sacc[nt][1]));
            tmax1 = fmaxf(tmax1, fmaxf(sacc[nt][2], sacc[nt][3]));
        }
        tmax0 = fmaxf(tmax0, __shfl_xor_sync(0xFFFFFFFFu, tmax0, 1));
        tmax0 = fmaxf(tmax0, __shfl_xor_sync(0xFFFFFFFFu, tmax0, 2));
        tmax1 = fmaxf(tmax1, __shfl_xor_sync(0xFFFFFFFFu, tmax1, 1));
        tmax1 = fmaxf(tmax1, __shfl_xor_sync(0xFFFFFFFFu, tmax1, 2));
        const float mn0 = fmaxf(m0, tmax0), mn1 = fmaxf(m1, tmax1);
        const float sc0 = __expf(m0 - mn0), sc1 = __expf(m1 - mn1);
        float sum0 = 0.f, sum1 = 0.f;
        #pragma unroll
        for (int nt = 0; nt < 8; nt++) {
            const float p00 = __expf(sacc[nt][0] - mn0);
            const float p01 = __expf(sacc[nt][1] - mn0);
            const float p10 = __expf(sacc[nt][2] - mn1);
            const float p11 = __expf(sacc[nt][3] - mn1);
            sum0 += p00 + p01; sum1 += p10 + p11;
            float2 s0; s0.x = f2tf32(p00); s0.y = f2tf32(p01);
            *reinterpret_cast<float2*>(Ps + qrow*VST + nt*8 + lr4*2) = s0;
            float2 s1; s1.x = f2tf32(p10); s1.y = f2tf32(p11);
            *reinterpret_cast<float2*>(Ps + (qrow+8)*VST + nt*8 + lr4*2) = s1;
        }
        sum0 += __shfl_xor_sync(0xFFFFFFFFu, sum0, 1);
        sum0 += __shfl_xor_sync(0xFFFFFFFFu, sum0, 2);
        sum1 += __shfl_xor_sync(0xFFFFFFFFu, sum1, 1);
        sum1 += __shfl_xor_sync(0xFFFFFFFFu, sum1, 2);
        l0 = l0*sc0 + sum0; l1 = l1*sc1 + sum1;
        m0 = mn0; m1 = mn1;
        #pragma unroll
        for (int d = 0; d < 16; d++) {
            oacc[d][0] *= sc0; oacc[d][1] *= sc0;
            oacc[d][2] *= sc1; oacc[d][3] *= sc1;
        }
        __syncwarp();

        #pragma unroll
        for (int ks = 0; ks < 8; ks++) {
            const int k = ks*8 + lr4;
            uint32_t af[4];
            af[0] = __float_as_uint(Ps[qrow*VST + k]);
            af[1] = __float_as_uint(Ps[(qrow+8)*VST + k]);
            af[2] = __float_as_uint(Ps[qrow*VST + k + 4]);
            af[3] = __float_as_uint(Ps[(qrow+8)*VST + k + 4]);
            #pragma unroll
            for (int d = 0; d < 16; d++) {
                uint32_t bf[2];
                bf[0] = __float_as_uint(Vt[(d*8 + lq)*VST + k]);
                bf[1] = __float_as_uint(Vt[(d*8 + lq)*VST + k + 4]);
                mma8(oacc[d], af, bf);
            }
        }
    }

    const float inv0 = 1.f / l0, inv1 = 1.f / l1;
    float* orow0 = g_attn + ((size_t)(b*QLEN + q0 + w*16 + lq))*HID + h*HD;
    float* orow1 = orow0 + (size_t)8*HID;
    #pragma unroll
    for (int d = 0; d < 16; d++) {
        float2 v0; v0.x = oacc[d][0]*inv0; v0.y = oacc[d][1]*inv0;
        *reinterpret_cast<float2*>(orow0 + d*8 + lr4*2) = v0;
        float2 v1; v1.x = oacc[d][2]*inv1; v1.y = oacc[d][3]*inv1;
        *reinterpret_cast<float2*>(orow1 + d*8 + lr4*2) = v1;
    }
}

// ---------------------------------------------------------------------------
extern "C" void kernel_launch(void* const* d_in, const int* in_sizes, int n_in,
                              void* d_out, int out_size)
{
    const float* hs = (const float*)d_in[0];
    const float* pk = (const float*)d_in[1];
    const float* pv = (const float*)d_in[2];
    const int*   mk = (const int*)  d_in[3];
    const float* Wq = (const float*)d_in[4];
    const float* bq = (const float*)d_in[5];
    const float* Wk = (const float*)d_in[6];
    const float* bk = (const float*)d_in[7];
    const float* Wv = (const float*)d_in[8];
    const float* bv = (const float*)d_in[9];
    const float* Wo = (const float*)d_in[10];
    const float* bo = (const float*)d_in[11];
    float* out = (float*)d_out;

    cudaFuncSetAttribute(qkv_mma, cudaFuncAttributeMaxDynamicSharedMemorySize, GSMEM);
    cudaFuncSetAttribute(out_mma, cudaFuncAttributeMaxDynamicSharedMemorySize, GSMEM);
    cudaFuncSetAttribute(attn_mma, cudaFuncAttributeMaxDynamicSharedMemorySize, ATTN_SM_BYTES);

    dim3 g1(MROWS/BM, 6144/BN);           // 32 x 96
    qkv_mma<<<g1, 256, GSMEM>>>(hs, Wq, bq, Wk, bk, Wv, bv);

    dim3 g2(QLEN/AQ, NH, NB);             // 8 x 32 x 4
    attn_mma<<<g2, 256, ATTN_SM_BYTES>>>(pk, pv, mk);

    dim3 g3(MROWS/BM, HID/BN);            // 32 x 64
    out_mma<<<g3, 256, GSMEM>>>(Wo, bo, out);
}

// round 8
// speedup vs baseline: 1.3769x; 1.3769x over previous
#include <cuda_runtime.h>
#include <cstdint>
#include <math.h>

// Problem constants
#define HID   4096
#define NB    4
#define QLEN  1024
#define NH    32
#define NKV   8
#define HD    128
#define PAST  1024
#define KVLEN 2048
#define MROWS (NB*QLEN)   // 4096
#define QSCALE 0.08838834764831845f
#define NEGBIG (-1.0e9f)

// GEMM tiling (mma.sync tf32): 128x128 CTA tile (R6 config), BK=16, 8 warps (4x2)
#define BM 128
#define BN 128
#define BK 16
#define NKITER (HID/BK)     // 256
#define SST 20              // smem row stride in floats (conflict-free, 80B = 16B-aligned rows)
#define TILEF (BM*SST)      // 2560 floats per buffer
#define TILEB (TILEF*4)     // bytes
#define GSMEM (4*TILEB)     // A0,A1,B0,B1 = 40960 bytes

// Attention tiling (unchanged from R6-passing kernel)
#define AQ  128
#define AKV 64
#define QST 132
#define VST 68
#define ATTN_SM_BYTES ((128*QST + 64*QST + 128*VST + 128*VST + 64) * 4)

// Scratch (device globals — allocation-free)
__device__ float g_q   [(size_t)NB*NH *QLEN*HD];   // [B,H,S,D]
__device__ float g_kn  [(size_t)NB*NKV*QLEN*HD];   // [B,Hkv,S,D]
__device__ float g_vn  [(size_t)NB*NKV*QLEN*HD];   // [B,Hkv,S,D]
__device__ float g_attn[(size_t)MROWS*HID];        // [B*S, H*D]

// ---------------------------------------------------------------------------
__device__ __forceinline__ float f2tf32(float x){
    uint32_t r; asm("cvt.rna.tf32.f32 %0, %1;" : "=r"(r) : "f"(x));
    return __uint_as_float(r);
}
__device__ __forceinline__ uint32_t smem_u32(const void* p){
    uint32_t a;
    asm("{ .reg .u64 t; cvta.to.shared.u64 t, %1; cvt.u32.u64 %0, t; }" : "=r"(a) : "l"(p));
    return a;
}
__device__ __forceinline__ void mma8(float* d, const uint32_t* a, const uint32_t* b){
    asm volatile(
        "mma.sync.aligned.m16n8k8.row.col.f32.tf32.tf32.f32 "
        "{%0,%1,%2,%3}, {%4,%5,%6,%7}, {%8,%9}, {%0,%1,%2,%3};"
        : "+f"(d[0]), "+f"(d[1]), "+f"(d[2]), "+f"(d[3])
        : "r"(a[0]), "r"(a[1]), "r"(a[2]), "r"(a[3]), "r"(b[0]), "r"(b[1]));
}
__device__ __forceinline__ void ldsm4(uint32_t addr, uint32_t& r0, uint32_t& r1,
                                      uint32_t& r2, uint32_t& r3){
    asm volatile("ldmatrix.sync.aligned.m8n8.x4.shared.b16 {%0,%1,%2,%3}, [%4];"
        : "=r"(r0), "=r"(r1), "=r"(r2), "=r"(r3) : "r"(addr));
}

// ---------------------------------------------------------------------------
// GEMM mainloop: C[128x128] = A[128 x 4096] @ B^T (B row-major [128][4096])
// Fragment loads via ldmatrix.x4 (each 8x4-b32 block = one 8x8-b16 matrix).
// ---------------------------------------------------------------------------
__device__ __forceinline__ void gemm_mainloop(
    const float* __restrict__ Ag, const float* __restrict__ Bg,
    float (&acc)[2][8][4])
{
    extern __shared__ float sm[];
    float* Abuf[2] = { sm,            sm + TILEF };
    float* Bbuf[2] = { sm + 2*TILEF,  sm + 3*TILEF };
    const uint32_t smbase = smem_u32(sm);

    const int tid  = threadIdx.x;
    const int lane = tid & 31;
    const int w    = tid >> 5;
    const int wm   = w & 3;
    const int wn   = w >> 2;

    #pragma unroll
    for (int mt = 0; mt < 2; mt++)
        #pragma unroll
        for (int nt = 0; nt < 8; nt++)
            #pragma unroll
            for (int c = 0; c < 4; c++) acc[mt][nt][c] = 0.f;

    // ldmatrix per-lane address components (byte offsets within a buffer)
    // A(mt): m0 rows r..r+7 cols kk..kk+3 | m1 rows +8 | m2 cols +4 | m3 rows+8,cols+4
    const int arow = wm*32 + (lane & 7) + ((lane >> 3) & 1) * 8;
    const int acol = (lane >> 4) * 4;
    const uint32_t aoff = (uint32_t)(arow*SST + acol) * 4u;
    // B(pair p): m0 rows nb..+7 cols kk (b0) | m1 rows nb..+7 cols kk+4 (b1)
    //            m2 rows nb+8..+15 cols kk | m3 rows nb+8 cols kk+4
    const int brow = wn*64 + (lane & 7) + (lane >> 4) * 8;
    const int bcol = ((lane >> 3) & 1) * 4;
    const uint32_t boff = (uint32_t)(brow*SST + bcol) * 4u;

    // staging: 512 float4 per matrix, 2 per thread
    const int f0 = tid, f1 = 256 + tid;
    const int r0 = f0 >> 2, c0 = (f0 & 3) * 4;
    const int r1 = f1 >> 2, c1 = (f1 & 3) * 4;

    float4 ra[2], rb[2];
    auto ld_tile = [&](int k0){
        ra[0] = *reinterpret_cast<const float4*>(Ag + (size_t)r0*HID + k0 + c0);
        ra[1] = *reinterpret_cast<const float4*>(Ag + (size_t)r1*HID + k0 + c1);
        rb[0] = *reinterpret_cast<const float4*>(Bg + (size_t)r0*HID + k0 + c0);
        rb[1] = *reinterpret_cast<const float4*>(Bg + (size_t)r1*HID + k0 + c1);
    };
    auto st_tile = [&](float* As, float* Bs){
        float4 v;
        v.x=f2tf32(ra[0].x); v.y=f2tf32(ra[0].y); v.z=f2tf32(ra[0].z); v.w=f2tf32(ra[0].w);
        *reinterpret_cast<float4*>(As + r0*SST + c0) = v;
        v.x=f2tf32(ra[1].x); v.y=f2tf32(ra[1].y); v.z=f2tf32(ra[1].z); v.w=f2tf32(ra[1].w);
        *reinterpret_cast<float4*>(As + r1*SST + c1) = v;
        v.x=f2tf32(rb[0].x); v.y=f2tf32(rb[0].y); v.z=f2tf32(rb[0].z); v.w=f2tf32(rb[0].w);
        *reinterpret_cast<float4*>(Bs + r0*SST + c0) = v;
        v.x=f2tf32(rb[1].x); v.y=f2tf32(rb[1].y); v.z=f2tf32(rb[1].z); v.w=f2tf32(rb[1].w);
        *reinterpret_cast<float4*>(Bs + r1*SST + c1) = v;
    };

    ld_tile(0);
    st_tile(Abuf[0], Bbuf[0]);
    __syncthreads();

    for (int kt = 0; kt < NKITER; kt++) {
        const bool last = (kt == NKITER - 1);
        if (!last) ld_tile((kt + 1) * BK);

        const uint32_t Aaddr = smbase + (uint32_t)(kt & 1)*TILEB + aoff;
        const uint32_t Baddr = smbase + (uint32_t)(2 + (kt & 1))*TILEB + boff;
        #pragma unroll
        for (int ks = 0; ks < 2; ks++) {
            const uint32_t kkB = (uint32_t)(ks * 8) * 4u;
            uint32_t af[2][4], bf[8][2];
            ldsm4(Aaddr + kkB,                 af[0][0], af[0][1], af[0][2], af[0][3]);
            ldsm4(Aaddr + 16*SST*4 + kkB,      af[1][0], af[1][1], af[1][2], af[1][3]);
            #pragma unroll
            for (int p = 0; p < 4; p++)
                ldsm4(Baddr + (uint32_t)(p*16*SST)*4u + kkB,
                      bf[2*p][0], bf[2*p][1], bf[2*p+1][0], bf[2*p+1][1]);
            #pragma unroll
            for (int mt = 0; mt < 2; mt++)
                #pragma unroll
                for (int nt = 0; nt < 8; nt++)
                    mma8(acc[mt][nt], af[mt], bf[nt]);
        }
        if (!last) st_tile(Abuf[(kt+1) & 1], Bbuf[(kt+1) & 1]);
        __syncthreads();
    }
}

// ---------------------------------------------------------------------------
// QKV projection: virtual N = 6144 (q 0..4095 | k 4096..5119 | v 5120..6143)
// ---------------------------------------------------------------------------
__global__ void __launch_bounds__(256, 2) qkv_mma(
    const float* __restrict__ X,
    const float* __restrict__ Wq, const float* __restrict__ bq,
    const float* __restrict__ Wk, const float* __restrict__ bk,
    const float* __restrict__ Wv, const float* __restrict__ bv)
{
    const int m0  = blockIdx.x * BM;
    const int n0e = blockIdx.y * BN;
    const float* W; const float* bias; int sel, nl0;
    if (n0e < 4096)      { W = Wq; bias = bq; sel = 0; nl0 = n0e; }
    else if (n0e < 5120) { W = Wk; bias = bk; sel = 1; nl0 = n0e - 4096; }
    else                 { W = Wv; bias = bv; sel = 2; nl0 = n0e - 5120; }

    float acc[2][8][4];
    gemm_mainloop(X + (size_t)m0*HID, W + (size_t)nl0*HID, acc);

    const int lane = threadIdx.x & 31, w = threadIdx.x >> 5;
    const int wm = w & 3, wn = w >> 2;
    const int lq = lane >> 2, lr4 = lane & 3;

    #pragma unroll
    for (int mt = 0; mt < 2; mt++) {
        #pragma unroll
        for (int half = 0; half < 2; half++) {
            const int gm = m0 + wm*32 + mt*16 + lq + half*8;
            const int bb = gm >> 10, sq = gm & 1023;
            #pragma unroll
            for (int nt = 0; nt < 8; nt++) {
                const int nl = nl0 + wn*64 + nt*8 + lr4*2;
                const float2 bv2 = *reinterpret_cast<const float2*>(bias + nl);
                float2 v;
                v.x = acc[mt][nt][half*2 + 0] + bv2.x;
                v.y = acc[mt][nt][half*2 + 1] + bv2.y;
                const int h = nl >> 7, d = nl & 127;
                float* dst;
                if (sel == 0)      dst = &g_q [(((size_t)bb*NH  + h)*QLEN + sq)*HD + d];
                else if (sel == 1) dst = &g_kn[(((size_t)bb*NKV + h)*QLEN + sq)*HD + d];
                else               dst = &g_vn[(((size_t)bb*NKV + h)*QLEN + sq)*HD + d];
                *reinterpret_cast<float2*>(dst) = v;
            }
        }
    }
}

// ---------------------------------------------------------------------------
// Output projection: out = g_attn @ Wo^T + bo
// ---------------------------------------------------------------------------
__global__ void __launch_bounds__(256, 2) out_mma(
    const float* __restrict__ Wo, const float* __restrict__ bo,
    float* __restrict__ out)
{
    const int m0 = blockIdx.x * BM;
    const int n0 = blockIdx.y * BN;

    float acc[2][8][4];
    gemm_mainloop(g_attn + (size_t)m0*HID, Wo + (size_t)n0*HID, acc);

    const int lane = threadIdx.x & 31, w = threadIdx.x >> 5;
    const int wm = w & 3, wn = w >> 2;
    const int lq = lane >> 2, lr4 = lane & 3;

    #pragma unroll
    for (int mt = 0; mt < 2; mt++) {
        #pragma unroll
        for (int half = 0; half < 2; half++) {
            const int gm = m0 + wm*32 + mt*16 + lq + half*8;
            #pragma unroll
            for (int nt = 0; nt < 8; nt++) {
                const int gn = n0 + wn*64 + nt*8 + lr4*2;
                const float2 bv2 = *reinterpret_cast<const float2*>(bo + gn);
                float2 v;
                v.x = acc[mt][nt][half*2 + 0] + bv2.x;
                v.y = acc[mt][nt][half*2 + 1] + bv2.y;
                *reinterpret_cast<float2*>(out + (size_t)gm*HID + gn) = v;
            }
        }
    }
}

// ---------------------------------------------------------------------------
// Flash attention on mma.sync tf32 (unchanged from R6-passing kernel)
// ---------------------------------------------------------------------------
__global__ void __launch_bounds__(256, 1) attn_mma(
    const float* __restrict__ pastK, const float* __restrict__ pastV,
    const int* __restrict__ amask)
{
    extern __shared__ float sm[];
    float* Qs = sm;                    // [128][QST]
    float* Ks = Qs + 128*QST;          // [64][QST]
    float* Vt = Ks + 64*QST;           // [128][VST]
    float* Ps = Vt + 128*VST;          // [128][VST]
    float* mb = Ps + 128*VST;          // [64]

    const int b = blockIdx.z, h = blockIdx.y, q0 = blockIdx.x * AQ;
    const int hkv = h >> 2;
    const int tid = threadIdx.x;
    const int lane = tid & 31, w = tid >> 5;
    const int lq = lane >> 2, lr4 = lane & 3;
    const int qrow = w*16 + lq;

    {
        const int r = tid >> 1;
        const int cb = (tid & 1) * 64;
        const float* Qg = g_q + (((size_t)b*NH + h)*QLEN + q0 + r) * HD + cb;
        #pragma unroll
        for (int i = 0; i < 16; i++) {
            float4 q = *reinterpret_cast<const float4*>(Qg + i*4);
            float4 v;
            v.x = f2tf32(q.x * QSCALE); v.y = f2tf32(q.y * QSCALE);
            v.z = f2tf32(q.z * QSCALE); v.w = f2tf32(q.w * QSCALE);
            *reinterpret_cast<float4*>(Qs + r*QST + cb + i*4) = v;
        }
    }

    float oacc[16][4];
    #pragma unroll
    for (int d = 0; d < 16; d++)
        #pragma unroll
        for (int c = 0; c < 4; c++) oacc[d][c] = 0.f;
    float m0 = -3.0e38f, m1 = -3.0e38f, l0 = 0.f, l1 = 0.f;

    const float* Kgp = pastK + ((size_t)b*NKV + hkv) * PAST * HD;
    const float* Vgp = pastV + ((size_t)b*NKV + hkv) * PAST * HD;
    const float* Kgn = g_kn  + ((size_t)b*NKV + hkv) * QLEN * HD;
    const float* Vgn = g_vn  + ((size_t)b*NKV + hkv) * QLEN * HD;
    const int*   mg  = amask + (size_t)b * KVLEN;

    for (int kt = 0; kt < 32; kt++) {
        __syncthreads();
        {
            const int r = tid & 63, c4 = tid >> 6;
            const int p = kt*64 + r;
            const float* krow = (p < PAST) ? (Kgp + (size_t)p*HD) : (Kgn + (size_t)(p-PAST)*HD);
            const float* vrow = (p < PAST) ? (Vgp + (size_t)p*HD) : (Vgn + (size_t)(p-PAST)*HD);
            #pragma unroll
            for (int i = 0; i < 8; i++) {
                const int cc = (c4 + i*4) * 4;
                float4 k4 = *reinterpret_cast<const float4*>(krow + cc);
                float4 kv;
                kv.x = f2tf32(k4.x); kv.y = f2tf32(k4.y);
                kv.z = f2tf32(k4.z); kv.w = f2tf32(k4.w);
                *reinterpret_cast<float4*>(Ks + r*QST + cc) = kv;
                float4 v4 = *reinterpret_cast<const float4*>(vrow + cc);
                Vt[(cc+0)*VST + r] = f2tf32(v4.x);
                Vt[(cc+1)*VST + r] = f2tf32(v4.y);
                Vt[(cc+2)*VST + r] = f2tf32(v4.z);
                Vt[(cc+3)*VST + r] = f2tf32(v4.w);
            }
            if (tid < 64) mb[tid] = (mg[kt*64 + tid] == 0) ? 0.f : NEGBIG;
        }
        __syncthreads();

        float sacc[8][4];
        #pragma unroll
        for (int nt = 0; nt < 8; nt++)
            #pragma unroll
            for (int c = 0; c < 4; c++) sacc[nt][c] = 0.f;
        #pragma unroll
        for (int ks = 0; ks < 16; ks++) {
            const int k = ks*8 + lr4;
            uint32_t af[4];
            af[0] = __float_as_uint(Qs[qrow*QST + k]);
            af[1] = __float_as_uint(Qs[(qrow+8)*QST + k]);
            af[2] = __float_as_uint(Qs[qrow*QST + k + 4]);
            af[3] = __float_as_uint(Qs[(qrow+8)*QST + k + 4]);
            #pragma unroll
            for (int nt = 0; nt < 8; nt++) {
                uint32_t bf[2];
                bf[0] = __float_as_uint(Ks[(nt*8 + lq)*QST + k]);
                bf[1] = __float_as_uint(Ks[(nt*8 + lq)*QST + k + 4]);
                mma8(sacc[nt], af, bf);
            }
        }

        float tmax0 = -3.0e38f, tmax1 = -3.0e38f;
        #pragma unroll
        for (int nt = 0; nt < 8; nt++) {
            const float b0 = mb[nt*8 + lr4*2], b1 = mb[nt*8 + lr4*2 + 1];
            sacc[nt][0] += b0; sacc[nt][1] += b1;
            sacc[nt][2] += b0; sacc[nt][3] += b1;
            tmax0 = fmaxf(tmax0, fmaxf(sacc[nt][0], sacc[nt][1]));
            tmax1 = fmaxf(tmax1, fmaxf(sacc[nt][2], sacc[nt][3]));
        }
        tmax0 = fmaxf(tmax0, __shfl_xor_sync(0xFFFFFFFFu, tmax0, 1));
        tmax0 = fmaxf(tmax0, __shfl_xor_sync(0xFFFFFFFFu, tmax0, 2));
        tmax1 = fmaxf(tmax1, __shfl_xor_sync(0xFFFFFFFFu, tmax1, 1));
        tmax1 = fmaxf(tmax1, __shfl_xor_sync(0xFFFFFFFFu, tmax1, 2));
        const float mn0 = fmaxf(m0, tmax0), mn1 = fmaxf(m1, tmax1);
        const float sc0 = __expf(m0 - mn0), sc1 = __expf(m1 - mn1);
        float sum0 = 0.f, sum1 = 0.f;
        #pragma unroll
        for (int nt = 0; nt < 8; nt++) {
            const float p00 = __expf(sacc[nt][0] - mn0);
            const float p01 = __expf(sacc[nt][1] - mn0);
            const float p10 = __expf(sacc[nt][2] - mn1);
            const float p11 = __expf(sacc[nt][3] - mn1);
            sum0 += p00 + p01; sum1 += p10 + p11;
            float2 s0; s0.x = f2tf32(p00); s0.y = f2tf32(p01);
            *reinterpret_cast<float2*>(Ps + qrow*VST + nt*8 + lr4*2) = s0;
            float2 s1; s1.x = f2tf32(p10); s1.y = f2tf32(p11);
            *reinterpret_cast<float2*>(Ps + (qrow+8)*VST + nt*8 + lr4*2) = s1;
        }
        sum0 += __shfl_xor_sync(0xFFFFFFFFu, sum0, 1);
        sum0 += __shfl_xor_sync(0xFFFFFFFFu, sum0, 2);
        sum1 += __shfl_xor_sync(0xFFFFFFFFu, sum1, 1);
        sum1 += __shfl_xor_sync(0xFFFFFFFFu, sum1, 2);
        l0 = l0*sc0 + sum0; l1 = l1*sc1 + sum1;
        m0 = mn0; m1 = mn1;
        #pragma unroll
        for (int d = 0; d < 16; d++) {
            oacc[d][0] *= sc0; oacc[d][1] *= sc0;
            oacc[d][2] *= sc1; oacc[d][3] *= sc1;
        }
        __syncwarp();

        #pragma unroll
        for (int ks = 0; ks < 8; ks++) {
            const int k = ks*8 + lr4;
            uint32_t af[4];
            af[0] = __float_as_uint(Ps[qrow*VST + k]);
            af[1] = __float_as_uint(Ps[(qrow+8)*VST + k]);
            af[2] = __float_as_uint(Ps[qrow*VST + k + 4]);
            af[3] = __float_as_uint(Ps[(qrow+8)*VST + k + 4]);
            #pragma unroll
            for (int d = 0; d < 16; d++) {
                uint32_t bf[2];
                bf[0] = __float_as_uint(Vt[(d*8 + lq)*VST + k]);
                bf[1] = __float_as_uint(Vt[(d*8 + lq)*VST + k + 4]);
                mma8(oacc[d], af, bf);
            }
        }
    }

    const float inv0 = 1.f / l0, inv1 = 1.f / l1;
    float* orow0 = g_attn + ((size_t)(b*QLEN + q0 + w*16 + lq))*HID + h*HD;
    float* orow1 = orow0 + (size_t)8*HID;
    #pragma unroll
    for (int d = 0; d < 16; d++) {
        float2 v0; v0.x = oacc[d][0]*inv0; v0.y = oacc[d][1]*inv0;
        *reinterpret_cast<float2*>(orow0 + d*8 + lr4*2) = v0;
        float2 v1; v1.x = oacc[d][2]*inv1; v1.y = oacc[d][3]*inv1;
        *reinterpret_cast<float2*>(orow1 + d*8 + lr4*2) = v1;
    }
}

// ---------------------------------------------------------------------------
extern "C" void kernel_launch(void* const* d_in, const int* in_sizes, int n_in,
                              void* d_out, int out_size)
{
    const float* hs = (const float*)d_in[0];
    const float* pk = (const float*)d_in[1];
    const float* pv = (const float*)d_in[2];
    const int*   mk = (const int*)  d_in[3];
    const float* Wq = (const float*)d_in[4];
    const float* bq = (const float*)d_in[5];
    const float* Wk = (const float*)d_in[6];
    const float* bk = (const float*)d_in[7];
    const float* Wv = (const float*)d_in[8];
    const float* bv = (const float*)d_in[9];
    const float* Wo = (const float*)d_in[10];
    const float* bo = (const float*)d_in[11];
    float* out = (float*)d_out;

    cudaFuncSetAttribute(qkv_mma, cudaFuncAttributeMaxDynamicSharedMemorySize, GSMEM);
    cudaFuncSetAttribute(out_mma, cudaFuncAttributeMaxDynamicSharedMemorySize, GSMEM);
    cudaFuncSetAttribute(attn_mma, cudaFuncAttributeMaxDynamicSharedMemorySize, ATTN_SM_BYTES);

    dim3 g1(MROWS/BM, 6144/BN);           // 32 x 48
    qkv_mma<<<g1, 256, GSMEM>>>(hs, Wq, bq, Wk, bk, Wv, bv);

    dim3 g2(QLEN/AQ, NH, NB);             // 8 x 32 x 4
    attn_mma<<<g2, 256, ATTN_SM_BYTES>>>(pk, pv, mk);

    dim3 g3(MROWS/BM, HID/BN);            // 32 x 32
    out_mma<<<g3, 256, GSMEM>>>(Wo, bo, out);
}